// round 5
// baseline (speedup 1.0000x reference)
#include <cuda_runtime.h>
#include <cstdint>

// Problem constants (fixed by the reference setup).
constexpr int B  = 32;
constexpr int H  = 512;
constexpr int W  = 512;
constexpr int HW = H * W;                  // 262144 per channel plane
constexpr int NPIX = B * HW;               // 8,388,608 pixels

// Tile geometry
constexpr int TW   = 128;                  // tile width (pixels)
constexpr int TH   = 32;                   // tile height
constexpr int HALO = 8;                    // displacement halo (N(0,1): |d|>7 ~ never)
constexpr int RW   = TW + 2 * HALO;        // 144  region width
constexpr int RH   = TH + 2 * HALO;        // 48   region height
constexpr int SSTR = RW + 1;               // 145  smem row stride (odd -> no bank aliasing)
constexpr int THREADS = 256;
constexpr int PPT  = TW * TH / THREADS;    // 16 pixels per thread
constexpr int TILES_X = W / TW;            // 4
constexpr int TILES_Y = H / TH;            // 16
constexpr int GRID = B * TILES_X * TILES_Y;            // 2048 blocks
constexpr int SMEM_BYTES = 2 * RH * SSTR * 4;          // 55,680 B
constexpr float INV_COUNT = 1.0f / (2.0f * (float)NPIX);

__device__ float g_partials[GRID];
__device__ int   g_count = 0;

__global__ __launch_bounds__(THREADS)
void cyc_loss_tiled(const float* __restrict__ fwd, const float* __restrict__ bwd,
                    float* __restrict__ out)
{
    extern __shared__ float sm[];
    float* __restrict__ s0 = sm;                     // channel 0 region
    float* __restrict__ s1 = sm + RH * SSTR;         // channel 1 region

    const int tid  = threadIdx.x;
    const int bid  = blockIdx.x;
    const int b    = bid >> 6;                       // image index (64 tiles/image)
    const int tile = bid & 63;
    const int tlx  = tile & (TILES_X - 1);           // tile x index (x-adjacent tiles = adjacent bids)
    const int tly  = tile >> 2;                      // tile y index

    const int rx0 = tlx * TW - HALO;                 // region origin (may be <0 / >W-RW)
    const int ry0 = tly * TH - HALO;

    const float* __restrict__ c0 = bwd + (size_t)b * 2 * HW;
    const float* __restrict__ c1 = c0 + HW;
    const float* __restrict__ fw = fwd + (size_t)b * 2 * HW;

    // ---------- Stage bwd region into smem (edge-clamped, coalesced) ----------
#pragma unroll
    for (int it = 0; it < (RW * RH) / THREADS; ++it) {       // 6912/256 = 27 iters
        const int idx = it * THREADS + tid;
        const int ry  = idx / RW;
        const int rx  = idx - ry * RW;
        const int gxi = min(max(rx0 + rx, 0), W - 1);
        const int gyi = min(max(ry0 + ry, 0), H - 1);
        const int off = gyi * W + gxi;
        s0[ry * SSTR + rx] = __ldg(c0 + off);
        s1[ry * SSTR + rx] = __ldg(c1 + off);
    }
    __syncthreads();

    // ---------- Gather + accumulate ----------
    const int tx = tid & (TW - 1);                   // lanes -> consecutive x
    const int ty_base = tid >> 7;                    // 0 or 1
    const int x  = tlx * TW + tx;

    float acc = 0.0f;
#pragma unroll 4
    for (int j = 0; j < PPT; ++j) {
        const int ty = ty_base + (j << 1);
        const int y  = tly * TH + ty;
        const int pix = y * W + x;

        const float dx = __ldg(fw + pix);
        const float dy = __ldg(fw + HW + pix);

        const float gx = fminf(fmaxf((float)x + dx, 0.0f), (float)(W - 1));
        const float gy = fminf(fmaxf((float)y + dy, 0.0f), (float)(H - 1));
        const int x0 = __float2int_rd(gx);
        const int y0 = __float2int_rd(gy);
        const float wx = gx - (float)x0;
        const float wy = gy - (float)y0;
        const int x1 = min(x0 + 1, W - 1);
        const int y1 = min(y0 + 1, H - 1);

        float a00, a01, a10, a11, b00, b01, b10, b11;
        const int sx0 = x0 - rx0, sy0 = y0 - ry0;
        const int sx1 = x1 - rx0, sy1 = y1 - ry0;

        if (__builtin_expect(sx0 >= 0 && sy0 >= 0 && sx1 < RW && sy1 < RH, 1)) {
            const int r0o = sy0 * SSTR;
            const int r1o = sy1 * SSTR;
            a00 = s0[r0o + sx0];  a01 = s0[r0o + sx1];
            a10 = s0[r1o + sx0];  a11 = s0[r1o + sx1];
            b00 = s1[r0o + sx0];  b01 = s1[r0o + sx1];
            b10 = s1[r1o + sx0];  b11 = s1[r1o + sx1];
        } else {
            // Out-of-halo displacement (essentially never): global fallback.
            const int i00 = y0 * W + x0, i01 = y0 * W + x1;
            const int i10 = y1 * W + x0, i11 = y1 * W + x1;
            a00 = __ldg(c0 + i00);  a01 = __ldg(c0 + i01);
            a10 = __ldg(c0 + i10);  a11 = __ldg(c0 + i11);
            b00 = __ldg(c1 + i00);  b01 = __ldg(c1 + i01);
            b10 = __ldg(c1 + i10);  b11 = __ldg(c1 + i11);
        }

        const float top0 = fmaf(wx, a01 - a00, a00);
        const float bot0 = fmaf(wx, a11 - a10, a10);
        const float s0v  = fmaf(wy, bot0 - top0, top0);
        const float top1 = fmaf(wx, b01 - b00, b00);
        const float bot1 = fmaf(wx, b11 - b10, b10);
        const float s1v  = fmaf(wy, bot1 - top1, top1);

        const float r0 = dx + s0v;
        const float r1 = dy + s1v;
        acc = fmaf(r0, r0, acc);
        acc = fmaf(r1, r1, acc);
    }

    // ---------- Block reduction (deterministic tree) ----------
    __shared__ float warp_sums[THREADS / 32];
#pragma unroll
    for (int off = 16; off > 0; off >>= 1)
        acc += __shfl_xor_sync(0xFFFFFFFFu, acc, off);

    const int lane = tid & 31;
    const int wid  = tid >> 5;
    if (lane == 0) warp_sums[wid] = acc;
    __syncthreads();

    __shared__ bool is_last;
    if (wid == 0) {
        float v = (lane < THREADS / 32) ? warp_sums[lane] : 0.0f;
#pragma unroll
        for (int off = 4; off > 0; off >>= 1)
            v += __shfl_xor_sync(0xFFFFFFFFu, v, off);
        if (lane == 0) {
            __stcg(&g_partials[blockIdx.x], v);
            __threadfence();
            const int prev = atomicAdd(&g_count, 1);
            is_last = (prev == GRID - 1);
        }
    }
    __syncthreads();

    // ---------- Last block: final reduction (fixed order -> deterministic) ----------
    if (is_last) {
        float v = 0.0f;
        for (int i = tid; i < GRID; i += THREADS)
            v += __ldcg(&g_partials[i]);

#pragma unroll
        for (int off = 16; off > 0; off >>= 1)
            v += __shfl_xor_sync(0xFFFFFFFFu, v, off);
        if (lane == 0) warp_sums[wid] = v;
        __syncthreads();

        if (wid == 0) {
            float s = (lane < THREADS / 32) ? warp_sums[lane] : 0.0f;
#pragma unroll
            for (int off = 4; off > 0; off >>= 1)
                s += __shfl_xor_sync(0xFFFFFFFFu, s, off);
            if (lane == 0) {
                out[0] = s * INV_COUNT;
                g_count = 0;
            }
        }
    }
}

extern "C" void kernel_launch(void* const* d_in, const int* in_sizes, int n_in,
                              void* d_out, int out_size)
{
    const float* fwd = (const float*)d_in[0];   // forward_disp  (B,2,H,W) fp32
    const float* bwd = (const float*)d_in[1];   // backward_disp (B,2,H,W) fp32
    float* out = (float*)d_out;

    static bool attr_set = false;
    if (!attr_set) {
        cudaFuncSetAttribute(cyc_loss_tiled,
                             cudaFuncAttributeMaxDynamicSharedMemorySize, SMEM_BYTES);
        attr_set = true;
    }
    cyc_loss_tiled<<<GRID, THREADS, SMEM_BYTES>>>(fwd, bwd, out);
}

// round 6
// speedup vs baseline: 1.2863x; 1.2863x over previous
#include <cuda_runtime.h>
#include <cstdint>

// Problem constants (fixed by the reference setup).
constexpr int B  = 32;
constexpr int H  = 512;
constexpr int W  = 512;
constexpr int HW = H * W;
constexpr int NPIX = B * HW;               // 8,388,608 pixels

// Tile geometry
constexpr int TW   = 64;                   // tile width
constexpr int TH   = 32;                   // tile height
constexpr int HALO = 6;                    // N(0,1): P(|d|>6) ~ 2e-9 -> fallback ~never
constexpr int RW   = TW + 2 * HALO;        // 76
constexpr int RH   = TH + 2 * HALO;        // 44
constexpr int SSTR = RW + 1;               // 77 float2 row stride (odd)
constexpr int THREADS = 256;
constexpr int PPT  = TW * TH / THREADS;    // 8 pixels per thread
constexpr int TILES_X = W / TW;            // 8
constexpr int TILES_Y = H / TH;            // 16
constexpr int GRID = B * TILES_X * TILES_Y;        // 4096 blocks
constexpr int SMEM_ELEMS = RH * SSTR;              // 3388 float2 = 27,104 B (< 48KB)
constexpr int REGION = RW * RH;                    // 3344 staged pixels
constexpr float INV_COUNT = 1.0f / (2.0f * (float)NPIX);

__device__ float g_partials[GRID];
__device__ int   g_count = 0;

__global__ __launch_bounds__(THREADS)
void cyc_loss_tiled(const float* __restrict__ fwd, const float* __restrict__ bwd,
                    float* __restrict__ out)
{
    __shared__ float2 sm[SMEM_ELEMS];

    const int tid  = threadIdx.x;
    const int bid  = blockIdx.x;
    const int b    = bid >> 7;                       // 128 tiles per image
    const int tile = bid & 127;
    const int tlx  = tile & (TILES_X - 1);           // x-adjacent tiles adjacent in bid
    const int tly  = tile >> 3;

    const int rx0 = tlx * TW - HALO;
    const int ry0 = tly * TH - HALO;

    const float* __restrict__ c0 = bwd + (size_t)b * 2 * HW;
    const float* __restrict__ c1 = c0 + HW;
    const float* __restrict__ fw = fwd + (size_t)b * 2 * HW;

    // ---------- Stage bwd region into smem as channel-interleaved float2 ----------
#pragma unroll
    for (int it = 0; it < (REGION + THREADS - 1) / THREADS; ++it) {   // 14 iters
        const int idx = it * THREADS + tid;
        if (idx < REGION) {
            const int ry  = idx / RW;
            const int rx  = idx - ry * RW;
            const int gxi = min(max(rx0 + rx, 0), W - 1);
            const int gyi = min(max(ry0 + ry, 0), H - 1);
            const int off = gyi * W + gxi;
            sm[ry * SSTR + rx] = make_float2(__ldg(c0 + off), __ldg(c1 + off));
        }
    }
    __syncthreads();

    // ---------- Gather + accumulate ----------
    const int tx = tid & (TW - 1);                   // lanes -> consecutive x
    const int ty_base = tid >> 6;                    // 0..3
    const int x  = tlx * TW + tx;

    float acc = 0.0f;
#pragma unroll
    for (int j = 0; j < PPT; ++j) {
        const int ty = ty_base + (j << 2);
        const int y  = tly * TH + ty;
        const int pix = y * W + x;

        const float dx = __ldg(fw + pix);
        const float dy = __ldg(fw + HW + pix);

        const float gx = fminf(fmaxf((float)x + dx, 0.0f), (float)(W - 1));
        const float gy = fminf(fmaxf((float)y + dy, 0.0f), (float)(H - 1));
        const int x0 = __float2int_rd(gx);
        const int y0 = __float2int_rd(gy);
        const float wx = gx - (float)x0;
        const float wy = gy - (float)y0;
        const int x1 = min(x0 + 1, W - 1);
        const int y1 = min(y0 + 1, H - 1);

        const int sx0 = x0 - rx0, sy0 = y0 - ry0;
        const int sx1 = x1 - rx0, sy1 = y1 - ry0;

        float2 v00, v01, v10, v11;
        if (__builtin_expect(sx0 >= 0 && sy0 >= 0 && sx1 < RW && sy1 < RH, 1)) {
            const int r0o = sy0 * SSTR;
            const int r1o = sy1 * SSTR;
            v00 = sm[r0o + sx0];  v01 = sm[r0o + sx1];
            v10 = sm[r1o + sx0];  v11 = sm[r1o + sx1];
        } else {
            // Out-of-halo displacement (essentially never): global fallback.
            const int i00 = y0 * W + x0, i01 = y0 * W + x1;
            const int i10 = y1 * W + x0, i11 = y1 * W + x1;
            v00 = make_float2(__ldg(c0 + i00), __ldg(c1 + i00));
            v01 = make_float2(__ldg(c0 + i01), __ldg(c1 + i01));
            v10 = make_float2(__ldg(c0 + i10), __ldg(c1 + i10));
            v11 = make_float2(__ldg(c0 + i11), __ldg(c1 + i11));
        }

        const float top0 = fmaf(wx, v01.x - v00.x, v00.x);
        const float bot0 = fmaf(wx, v11.x - v10.x, v10.x);
        const float s0v  = fmaf(wy, bot0 - top0, top0);
        const float top1 = fmaf(wx, v01.y - v00.y, v00.y);
        const float bot1 = fmaf(wx, v11.y - v10.y, v10.y);
        const float s1v  = fmaf(wy, bot1 - top1, top1);

        const float r0 = dx + s0v;
        const float r1 = dy + s1v;
        acc = fmaf(r0, r0, acc);
        acc = fmaf(r1, r1, acc);
    }

    // ---------- Block reduction (deterministic tree) ----------
    __shared__ float warp_sums[THREADS / 32];
#pragma unroll
    for (int off = 16; off > 0; off >>= 1)
        acc += __shfl_xor_sync(0xFFFFFFFFu, acc, off);

    const int lane = tid & 31;
    const int wid  = tid >> 5;
    if (lane == 0) warp_sums[wid] = acc;
    __syncthreads();

    __shared__ bool is_last;
    if (wid == 0) {
        float v = (lane < THREADS / 32) ? warp_sums[lane] : 0.0f;
#pragma unroll
        for (int off = 4; off > 0; off >>= 1)
            v += __shfl_xor_sync(0xFFFFFFFFu, v, off);
        if (lane == 0) {
            __stcg(&g_partials[blockIdx.x], v);
            __threadfence();
            const int prev = atomicAdd(&g_count, 1);
            is_last = (prev == GRID - 1);
        }
    }
    __syncthreads();

    // ---------- Last block: final reduction (fixed order -> deterministic) ----------
    if (is_last) {
        float v = 0.0f;
        for (int i = tid; i < GRID; i += THREADS)
            v += __ldcg(&g_partials[i]);

#pragma unroll
        for (int off = 16; off > 0; off >>= 1)
            v += __shfl_xor_sync(0xFFFFFFFFu, v, off);
        if (lane == 0) warp_sums[wid] = v;
        __syncthreads();

        if (wid == 0) {
            float s = (lane < THREADS / 32) ? warp_sums[lane] : 0.0f;
#pragma unroll
            for (int off = 4; off > 0; off >>= 1)
                s += __shfl_xor_sync(0xFFFFFFFFu, s, off);
            if (lane == 0) {
                out[0] = s * INV_COUNT;
                g_count = 0;
            }
        }
    }
}

extern "C" void kernel_launch(void* const* d_in, const int* in_sizes, int n_in,
                              void* d_out, int out_size)
{
    const float* fwd = (const float*)d_in[0];   // forward_disp  (B,2,H,W) fp32
    const float* bwd = (const float*)d_in[1];   // backward_disp (B,2,H,W) fp32
    float* out = (float*)d_out;

    cyc_loss_tiled<<<GRID, THREADS>>>(fwd, bwd, out);
}